// round 12
// baseline (speedup 1.0000x reference)
#include <cuda_runtime.h>

// Sinkhorn transport plan, L=64, B=7, 200 iterations, EPS=0.02.
// Log2-domain throughout (linear domain underflows: verified R3 failure).
//
// R9 loop body (57.4us baseline): single warp, lane r owns rows r and r+32.
//   f-update: in-lane logsumexp over 7 (max tree + ex2 + sum tree + lg2)
//   g-update: exact column max via __reduce_max_sync on order-preserving s32
//             keys, ex2, 5-level shuffle-add butterfly, lg2.
// New: period-2 cycle detection, exactly result-preserving:
//   If G_t == G_{t-2} bitwise, the deterministic iteration map is periodic
//   (period 2) from t-2 onward, so the state after iteration 199 equals the
//   state after the nearest same-parity iteration >= t. We compare each new G
//   against the G from two iterations ago (parity buffers GA/GB); a hit on
//   the wrong parity simply runs one more iteration and re-fires.

#define BB 7
#define NITER 200

__device__ __forceinline__ float ex2(float x) {
    float y; asm("ex2.approx.ftz.f32 %0, %1;" : "=f"(y) : "f"(x)); return y;
}
__device__ __forceinline__ float lg2(float x) {
    float y; asm("lg2.approx.ftz.f32 %0, %1;" : "=f"(y) : "f"(x)); return y;
}
// Exact warp-wide float max via s32 redux with a monotonic, self-inverse key.
__device__ __forceinline__ float warp_max(float x) {
    int b = __float_as_int(x);
    int k = b ^ ((b >> 31) & 0x7fffffff);
    int r = __reduce_max_sync(0xffffffffu, k);
    return __int_as_float(r ^ ((r >> 31) & 0x7fffffff));
}

__global__ __launch_bounds__(32, 1)
void sinkhorn_kernel(const float* __restrict__ theta,
                     const float* __restrict__ phi,
                     const float* __restrict__ nbuf,
                     const float* __restrict__ sens,
                     const float* __restrict__ err,
                     float* __restrict__ out)
{
    const unsigned FULL = 0xffffffffu;
    const int lane = threadIdx.x;
    const int r0 = lane, r1 = lane + 32;
    const float TINY = 1e-40f;
    const float L2E = 1.4426950408889634f;     // log2(e)
    const float SCALE = 72.13475204444817f;    // log2(e)/EPS

    // ---- load inputs ----
    float n0 = nbuf[r0], n1 = nbuf[r1];
    float se0 = sens[r0], se1 = sens[r1];
    float ev[BB], pv[BB];
    #pragma unroll
    for (int j = 0; j < BB; ++j) { ev[j] = err[j]; pv[j] = phi[j]; }

    // ---- a = n / sum(n); log2 a ----
    float sn = n0 + n1;
    #pragma unroll
    for (int o = 16; o > 0; o >>= 1) sn += __shfl_xor_sync(FULL, sn, o);
    float la0 = lg2(n0 / sn + TINY);
    float la1 = lg2(n1 / sn + TINY);

    // ---- b = softmax(phi); log2 b (replicated per lane) ----
    float pm = pv[0];
    #pragma unroll
    for (int j = 1; j < BB; ++j) pm = fmaxf(pm, pv[j]);
    float ps = 0.f, pe[BB];
    #pragma unroll
    for (int j = 0; j < BB; ++j) { pe[j] = ex2((pv[j] - pm) * L2E); ps += pe[j]; }
    float inv_ps = 1.0f / ps;
    float lb2[BB];
    #pragma unroll
    for (int j = 0; j < BB; ++j) lb2[j] = lg2(pe[j] * inv_ps + TINY);

    // ---- K2 = (theta - n*sens*err) * log2(e)/EPS ----
    float c0 = n0 * se0, c1 = n1 * se1;
    float K20[BB], K21[BB];
    #pragma unroll
    for (int j = 0; j < BB; ++j) {
        K20[j] = (theta[r0 * BB + j] - c0 * ev[j]) * SCALE;
        K21[j] = (theta[r1 * BB + j] - c1 * ev[j]) * SCALE;
    }

    // ---- Sinkhorn iterations ----
    float F0 = 0.f, F1 = 0.f, G[BB];
    float GA[BB], GB[BB];
    const float SENT = __int_as_float(0x7f800001);  // NaN sentinel, never equal
    #pragma unroll
    for (int j = 0; j < BB; ++j) { G[j] = 0.f; GA[j] = SENT; GB[j] = SENT; }

    // One Sinkhorn iteration; compares the new G (bitwise) against *buf
    // (G from two iterations ago) and refreshes buf. Returns true on a hit.
    auto body = [&](float* buf) -> bool {
        // f = la - log2sumexp2_j(K2 + G)   (in-lane, 7 per row)
        float t0[BB], t1[BB];
        #pragma unroll
        for (int j = 0; j < BB; ++j) {
            t0[j] = K20[j] + G[j];
            t1[j] = K21[j] + G[j];
        }
        float m0 = fmaxf(fmaxf(fmaxf(t0[0], t0[1]), fmaxf(t0[2], t0[3])),
                         fmaxf(fmaxf(t0[4], t0[5]), t0[6]));
        float m1 = fmaxf(fmaxf(fmaxf(t1[0], t1[1]), fmaxf(t1[2], t1[3])),
                         fmaxf(fmaxf(t1[4], t1[5]), t1[6]));
        float e0[BB], e1[BB];
        #pragma unroll
        for (int j = 0; j < BB; ++j) {
            e0[j] = ex2(t0[j] - m0);
            e1[j] = ex2(t1[j] - m1);
        }
        float s0 = ((e0[0] + e0[1]) + (e0[2] + e0[3])) + ((e0[4] + e0[5]) + e0[6]);
        float s1 = ((e1[0] + e1[1]) + (e1[2] + e1[3])) + ((e1[4] + e1[5]) + e1[6]);
        F0 = la0 - (m0 + lg2(s0));
        F1 = la1 - (m1 + lg2(s1));

        // g = lb - log2sumexp2_i(K2 + F)   (column reduction over the warp)
        float v0[BB], v1[BB], mm[BB];
        #pragma unroll
        for (int j = 0; j < BB; ++j) {
            v0[j] = K20[j] + F0;
            v1[j] = K21[j] + F1;
            mm[j] = warp_max(fmaxf(v0[j], v1[j]));   // exact column max
        }
        float s[BB];
        #pragma unroll
        for (int j = 0; j < BB; ++j)
            s[j] = ex2(v0[j] - mm[j]) + ex2(v1[j] - mm[j]);
        #pragma unroll
        for (int o = 16; o > 0; o >>= 1) {
            #pragma unroll
            for (int j = 0; j < BB; ++j)
                s[j] += __shfl_xor_sync(FULL, s[j], o);
        }
        bool same = true;
        #pragma unroll
        for (int j = 0; j < BB; ++j) {
            float gn = lb2[j] - (mm[j] + lg2(s[j]));
            same &= (__float_as_int(gn) == __float_as_int(buf[j]));
            buf[j] = gn;
            G[j] = gn;
        }
        return same;
    };

    #pragma unroll 1
    for (int p = 0; p < NITER / 2; ++p) {
        // even iteration (it = 2p): on a period-2 hit, the final (odd) state
        // is one more iteration away -> run it and stop.
        if (body(GA)) { body(GB); break; }
        // odd iteration (it = 2p+1): a hit means current state == state after
        // iteration 199 (same parity) -> stop.
        if (body(GB)) break;
    }

    // ---- P = exp2(K2 + F + G); normalize by global sum + TINY ----
    float P0[BB], P1[BB];
    float psum = 0.f;
    #pragma unroll
    for (int j = 0; j < BB; ++j) {
        P0[j] = ex2(K20[j] + F0 + G[j]);
        P1[j] = ex2(K21[j] + F1 + G[j]);
        psum += P0[j] + P1[j];
    }
    #pragma unroll
    for (int o = 16; o > 0; o >>= 1) psum += __shfl_xor_sync(FULL, psum, o);
    float inv = 1.0f / (psum + TINY);
    #pragma unroll
    for (int j = 0; j < BB; ++j) {
        out[r0 * BB + j] = P0[j] * inv;
        out[r1 * BB + j] = P1[j] * inv;
    }
}

extern "C" void kernel_launch(void* const* d_in, const int* in_sizes, int n_in,
                              void* d_out, int out_size) {
    const float* theta = (const float*)d_in[0];
    const float* phi   = (const float*)d_in[1];
    const float* n     = (const float*)d_in[2];
    const float* sens  = (const float*)d_in[3];
    const float* err   = (const float*)d_in[4];
    sinkhorn_kernel<<<1, 32>>>(theta, phi, n, sens, err, (float*)d_out);
}

// round 16
// speedup vs baseline: 1.2506x; 1.2506x over previous
#include <cuda_runtime.h>

// Sinkhorn transport plan, L=64, B=7, 200 iterations, EPS=0.02.
// Log2-domain throughout (linear domain underflows: verified R3 failure).
// Single warp; lane r owns rows r and r+32 in registers.
//
// Phase A (24 iters): exact R9 body — row max tree + redux-max column
//   stabilizers. Puts F,G at converged magnitude.
// Phase B (176 iters): stale-stabilizer updates. The logsumexp stabilizer
//   need not be the exact max — any common value M works exactly (it cancels
//   in M + log2(sum 2^(v-M))) provided arguments stay in range. At steady
//   state column lse == lb2_j - G_j, so M_j = lb2_j - G_j + 16 from the
//   previous iteration is a free stabilizer: arguments ~ -16 +/- drift.
//   All max machinery (redux, keys, trees) vanishes from the loop.
//   Clamps ex2(min(.,60)) / lg2(max(.,1e-30)) keep everything finite under
//   any transient drift; clamped iterations are bounded perturbations and
//   Sinkhorn self-corrects afterwards.

#define BB 7
#define NITER 200
#define PH1 24

__device__ __forceinline__ float ex2(float x) {
    float y; asm("ex2.approx.ftz.f32 %0, %1;" : "=f"(y) : "f"(x)); return y;
}
__device__ __forceinline__ float lg2(float x) {
    float y; asm("lg2.approx.ftz.f32 %0, %1;" : "=f"(y) : "f"(x)); return y;
}
// Exact warp-wide float max via s32 redux with a monotonic, self-inverse key.
__device__ __forceinline__ float warp_max(float x) {
    int b = __float_as_int(x);
    int k = b ^ ((b >> 31) & 0x7fffffff);
    int r = __reduce_max_sync(0xffffffffu, k);
    return __int_as_float(r ^ ((r >> 31) & 0x7fffffff));
}

__global__ __launch_bounds__(32, 1)
void sinkhorn_kernel(const float* __restrict__ theta,
                     const float* __restrict__ phi,
                     const float* __restrict__ nbuf,
                     const float* __restrict__ sens,
                     const float* __restrict__ err,
                     float* __restrict__ out)
{
    const unsigned FULL = 0xffffffffu;
    const int lane = threadIdx.x;
    const int r0 = lane, r1 = lane + 32;
    const float TINY = 1e-40f;
    const float L2E = 1.4426950408889634f;     // log2(e)
    const float SCALE = 72.13475204444817f;    // log2(e)/EPS
    const float MARGIN = 16.0f;
    const float CLAMP = 60.0f;
    const float SFLOOR = 1e-30f;

    // ---- load inputs ----
    float n0 = nbuf[r0], n1 = nbuf[r1];
    float se0 = sens[r0], se1 = sens[r1];
    float ev[BB], pv[BB];
    #pragma unroll
    for (int j = 0; j < BB; ++j) { ev[j] = err[j]; pv[j] = phi[j]; }

    // ---- a = n / sum(n); log2 a ----
    float sn = n0 + n1;
    #pragma unroll
    for (int o = 16; o > 0; o >>= 1) sn += __shfl_xor_sync(FULL, sn, o);
    float la0 = lg2(n0 / sn + TINY);
    float la1 = lg2(n1 / sn + TINY);

    // ---- b = softmax(phi); log2 b (replicated per lane) ----
    float pm = pv[0];
    #pragma unroll
    for (int j = 1; j < BB; ++j) pm = fmaxf(pm, pv[j]);
    float ps = 0.f, pe[BB];
    #pragma unroll
    for (int j = 0; j < BB; ++j) { pe[j] = ex2((pv[j] - pm) * L2E); ps += pe[j]; }
    float inv_ps = 1.0f / ps;
    float lb2[BB];
    #pragma unroll
    for (int j = 0; j < BB; ++j) lb2[j] = lg2(pe[j] * inv_ps + TINY);

    // ---- K2 = (theta - n*sens*err) * log2(e)/EPS ----
    float c0 = n0 * se0, c1 = n1 * se1;
    float K20[BB], K21[BB];
    #pragma unroll
    for (int j = 0; j < BB; ++j) {
        K20[j] = (theta[r0 * BB + j] - c0 * ev[j]) * SCALE;
        K21[j] = (theta[r1 * BB + j] - c1 * ev[j]) * SCALE;
    }

    float F0 = 0.f, F1 = 0.f, G[BB];
    #pragma unroll
    for (int j = 0; j < BB; ++j) G[j] = 0.f;

    // ================= Phase A: exact iterations =================
    #pragma unroll 1
    for (int it = 0; it < PH1; ++it) {
        float t0[BB], t1[BB];
        #pragma unroll
        for (int j = 0; j < BB; ++j) {
            t0[j] = K20[j] + G[j];
            t1[j] = K21[j] + G[j];
        }
        float m0 = fmaxf(fmaxf(fmaxf(t0[0], t0[1]), fmaxf(t0[2], t0[3])),
                         fmaxf(fmaxf(t0[4], t0[5]), t0[6]));
        float m1 = fmaxf(fmaxf(fmaxf(t1[0], t1[1]), fmaxf(t1[2], t1[3])),
                         fmaxf(fmaxf(t1[4], t1[5]), t1[6]));
        float e0[BB], e1[BB];
        #pragma unroll
        for (int j = 0; j < BB; ++j) {
            e0[j] = ex2(t0[j] - m0);
            e1[j] = ex2(t1[j] - m1);
        }
        float s0 = ((e0[0] + e0[1]) + (e0[2] + e0[3])) + ((e0[4] + e0[5]) + e0[6]);
        float s1 = ((e1[0] + e1[1]) + (e1[2] + e1[3])) + ((e1[4] + e1[5]) + e1[6]);
        F0 = la0 - (m0 + lg2(s0));
        F1 = la1 - (m1 + lg2(s1));

        float v0[BB], v1[BB], mm[BB];
        #pragma unroll
        for (int j = 0; j < BB; ++j) {
            v0[j] = K20[j] + F0;
            v1[j] = K21[j] + F1;
            mm[j] = warp_max(fmaxf(v0[j], v1[j]));
        }
        float s[BB];
        #pragma unroll
        for (int j = 0; j < BB; ++j)
            s[j] = ex2(v0[j] - mm[j]) + ex2(v1[j] - mm[j]);
        #pragma unroll
        for (int o = 16; o > 0; o >>= 1) {
            #pragma unroll
            for (int j = 0; j < BB; ++j)
                s[j] += __shfl_xor_sync(FULL, s[j], o);
        }
        #pragma unroll
        for (int j = 0; j < BB; ++j)
            G[j] = lb2[j] - (mm[j] + lg2(s[j]));
    }

    // ================= Phase B: stale-stabilizer iterations =================
    float Mf0 = la0 - F0 + MARGIN;
    float Mf1 = la1 - F1 + MARGIN;
    float Mg[BB];
    #pragma unroll
    for (int j = 0; j < BB; ++j) Mg[j] = lb2[j] - G[j] + MARGIN;

    #pragma unroll 1
    for (int it = PH1; it < NITER; ++it) {
        // f-update: stabilizer is last iteration's row-lse estimate.
        float e0[BB], e1[BB];
        #pragma unroll
        for (int j = 0; j < BB; ++j) {
            e0[j] = ex2(fminf((K20[j] + G[j]) - Mf0, CLAMP));
            e1[j] = ex2(fminf((K21[j] + G[j]) - Mf1, CLAMP));
        }
        float s0 = ((e0[0] + e0[1]) + (e0[2] + e0[3])) + ((e0[4] + e0[5]) + e0[6]);
        float s1 = ((e1[0] + e1[1]) + (e1[2] + e1[3])) + ((e1[4] + e1[5]) + e1[6]);
        F0 = la0 - (Mf0 + lg2(fmaxf(s0, SFLOOR)));
        F1 = la1 - (Mf1 + lg2(fmaxf(s1, SFLOOR)));
        Mf0 = la0 - F0 + MARGIN;
        Mf1 = la1 - F1 + MARGIN;

        // g-update: stabilizer is last iteration's column-lse estimate.
        float s[BB];
        #pragma unroll
        for (int j = 0; j < BB; ++j)
            s[j] = ex2(fminf((K20[j] + F0) - Mg[j], CLAMP)) +
                   ex2(fminf((K21[j] + F1) - Mg[j], CLAMP));
        #pragma unroll
        for (int o = 16; o > 0; o >>= 1) {
            #pragma unroll
            for (int j = 0; j < BB; ++j)
                s[j] += __shfl_xor_sync(FULL, s[j], o);
        }
        #pragma unroll
        for (int j = 0; j < BB; ++j) {
            G[j] = lb2[j] - (Mg[j] + lg2(fmaxf(s[j], SFLOOR)));
            Mg[j] = lb2[j] - G[j] + MARGIN;
        }
    }

    // ---- P = exp2(K2 + F + G); normalize by global sum + TINY ----
    float P0[BB], P1[BB];
    float psum = 0.f;
    #pragma unroll
    for (int j = 0; j < BB; ++j) {
        P0[j] = ex2(K20[j] + F0 + G[j]);
        P1[j] = ex2(K21[j] + F1 + G[j]);
        psum += P0[j] + P1[j];
    }
    #pragma unroll
    for (int o = 16; o > 0; o >>= 1) psum += __shfl_xor_sync(FULL, psum, o);
    float inv = 1.0f / (psum + TINY);
    #pragma unroll
    for (int j = 0; j < BB; ++j) {
        out[r0 * BB + j] = P0[j] * inv;
        out[r1 * BB + j] = P1[j] * inv;
    }
}

extern "C" void kernel_launch(void* const* d_in, const int* in_sizes, int n_in,
                              void* d_out, int out_size) {
    const float* theta = (const float*)d_in[0];
    const float* phi   = (const float*)d_in[1];
    const float* n     = (const float*)d_in[2];
    const float* sens  = (const float*)d_in[3];
    const float* err   = (const float*)d_in[4];
    sinkhorn_kernel<<<1, 32>>>(theta, phi, n, sens, err, (float*)d_out);
}